// round 11
// baseline (speedup 1.0000x reference)
#include <cuda_runtime.h>
#include <cstdint>

#define FULL 0xffffffffu
typedef unsigned long long u64;

// ---- packed f32x2 helpers (Blackwell FFMA2 — only reachable via PTX) ----
__device__ __forceinline__ u64 pk2(float lo, float hi) {
    u64 r;
    asm("mov.b64 %0, {%1, %2};" : "=l"(r) : "f"(lo), "f"(hi));
    return r;
}
__device__ __forceinline__ float2 upk2(u64 p) {
    float2 v;
    asm("mov.b64 {%0, %1}, %2;" : "=f"(v.x), "=f"(v.y) : "l"(p));
    return v;
}
__device__ __forceinline__ u64 fma2(u64 a, u64 b, u64 c) {
    u64 d;
    asm("fma.rn.f32x2 %0, %1, %2, %3;" : "=l"(d) : "l"(a), "l"(b), "l"(c));
    return d;
}
__device__ __forceinline__ u64 mul2(u64 a, u64 b) {
    u64 d;
    asm("mul.rn.f32x2 %0, %1, %2;" : "=l"(d) : "l"(a), "l"(b));
    return d;
}

// Fused split-K kernel, 8 rows per 256-thread block, grid = nrows/8.
// Phase 1: warp w owns j-slice [w*128,w*128+128); W1 slice register-resident in
//   XOR (rotated) layout: lane L slot k holds qubit (L&7)^k. The reduce-scatter
//   is then SEL-free: v[k] += shfl_xor(v[k^w], w) with compile-time indices;
//   lane L ends with qubit L&7 fully reduced in v[0].
// Quantum (threads 0..63): z = cos(th)cos(a) - sin(th)sin(phi)sin(a);
//   CNOT ring conjugated to Z-strings -> qout via octet prefix products.
// Phase 2: thread owns e0 = tid*4; W2 rows register-resident; bias folded into
//   packed accumulator; per row: 2 broadcast LDS + 16 FFMA2 + 1 STG.128.
__global__ void __launch_bounds__(256, 3)
ffq_kernel(const float* __restrict__ x,  const float* __restrict__ W1,
           const float* __restrict__ b1, const float* __restrict__ qp,
           const float* __restrict__ W2, const float* __restrict__ b2,
           float* __restrict__ out, int nrows)
{
    __shared__ __align__(16) float part[8][8][8];   // [row][qubit][warp]
    __shared__ __align__(16) float sq[8][8];        // qout per row

    const int tid  = threadIdx.x;
    const int lane = tid & 31;
    const int wid  = tid >> 5;
    const int rowblk = blockIdx.x * 8;

    const int j0 = wid * 128 + lane * 4;   // this lane's 4 j's
    const int qoct = lane & 7;

    // ---------------- Phase 1: split-K GEMM1, W1 reg-resident (XOR layout) ----------------
    u64 wp0[8], wp1[8];
#pragma unroll
    for (int k = 0; k < 8; k++) {
        const int i = qoct ^ k;   // slot k of lane L <-> W1 row (L&7)^k
        longlong2 w = __ldg((const longlong2*)(W1 + (size_t)i * 1024 + j0));
        wp0[k] = (u64)w.x;
        wp1[k] = (u64)w.y;
    }

#pragma unroll 4
    for (int rloc = 0; rloc < 8; rloc++) {
        const int row = min(rowblk + rloc, nrows - 1);
        longlong2 xv = __ldg((const longlong2*)(x + (size_t)row * 1024 + j0));
        const u64 x0 = (u64)xv.x, x1 = (u64)xv.y;

        float v[8];
#pragma unroll
        for (int k = 0; k < 8; k++) {
            u64 s = mul2(x0, wp0[k]);
            s = fma2(x1, wp1[k], s);
            float2 f = upk2(s);
            v[k] = f.x + f.y;
        }

        // SEL-free XOR reduce-scatter: after this, lane L's v[0] = full sum
        // for qubit L&7 (summed over all 32 lanes of this warp's j-slice).
        v[0] += __shfl_xor_sync(FULL, v[1], 1, 32);
        v[2] += __shfl_xor_sync(FULL, v[3], 1, 32);
        v[4] += __shfl_xor_sync(FULL, v[5], 1, 32);
        v[6] += __shfl_xor_sync(FULL, v[7], 1, 32);
        v[0] += __shfl_xor_sync(FULL, v[2], 2, 32);
        v[4] += __shfl_xor_sync(FULL, v[6], 2, 32);
        v[0] += __shfl_xor_sync(FULL, v[4], 4, 32);
        v[0] += __shfl_xor_sync(FULL, v[0], 8, 32);
        v[0] += __shfl_xor_sync(FULL, v[0], 16, 32);

        if (lane < 8) part[rloc][lane][wid] = v[0];
    }
    __syncthreads();

    // ---------------- Quantum: one thread per (row, qubit) ----------------
    if (tid < 64) {
        const int r  = tid >> 3;
        const int qi = tid & 7;

        const float4 pa = *(const float4*)&part[r][qi][0];
        const float4 pb = *(const float4*)&part[r][qi][4];
        const float a = ((pa.x + pa.y) + (pa.z + pa.w))
                      + ((pb.x + pb.y) + (pb.z + pb.w)) + __ldg(b1 + qi);

        const float phi   = __ldg(qp + 3 * qi);
        const float theta = __ldg(qp + 3 * qi + 1);
        const float k1 = cosf(theta);
        const float k2 = sinf(theta) * sinf(phi);

        float sa, ca;
        __sincosf(a, &sa, &ca);
        const float z = k1 * ca - k2 * sa;

        // inclusive prefix product over each 8-lane octet
        float p = z;
#pragma unroll
        for (int d = 1; d < 8; d <<= 1) {
            float t = __shfl_up_sync(FULL, p, d, 8);
            if (qi >= d) p *= t;
        }
        // second scan with z0 -> 1 for qout[0] = z1..z7
        float wv = (qi == 0) ? 1.0f : z;
#pragma unroll
        for (int d = 1; d < 8; d <<= 1) {
            float t = __shfl_up_sync(FULL, wv, d, 8);
            if (qi >= d) wv *= t;
        }
        const float pb7 = __shfl_sync(FULL, wv, 7, 8);
        sq[r][qi] = (qi == 0) ? pb7 : p;
    }
    __syncthreads();

    // ---------------- Phase 2: GEMM2, W2 reg-resident, bias folded ----------------
    const int e0 = tid * 4;   // 4 consecutive output columns per thread

    u64 w2r[4][4];
    u64 bvp[4];
#pragma unroll
    for (int k = 0; k < 4; k++) {
        longlong2 a = __ldg((const longlong2*)(W2 + (size_t)(e0 + k) * 8));
        longlong2 b = __ldg((const longlong2*)(W2 + (size_t)(e0 + k) * 8 + 4));
        w2r[k][0] = (u64)a.x;
        w2r[k][1] = (u64)a.y;
        w2r[k][2] = (u64)b.x;
        w2r[k][3] = (u64)b.y;
    }
    {
        float4 bv = __ldg((const float4*)(b2 + e0));
        bvp[0] = pk2(bv.x, 0.0f);
        bvp[1] = pk2(bv.y, 0.0f);
        bvp[2] = pk2(bv.z, 0.0f);
        bvp[3] = pk2(bv.w, 0.0f);
    }

#pragma unroll 4
    for (int rloc = 0; rloc < 8; rloc++) {
        const int row = rowblk + rloc;
        if (row >= nrows) break;

        const longlong2* sp = (const longlong2*)sq[rloc];   // broadcast LDS x2
        longlong2 qa = sp[0], qb = sp[1];
        const u64 qd0 = (u64)qa.x, qd1 = (u64)qa.y;
        const u64 qd2 = (u64)qb.x, qd3 = (u64)qb.y;

        float o[4];
#pragma unroll
        for (int k = 0; k < 4; k++) {
            u64 s = fma2(w2r[k][0], qd0, bvp[k]);
            s = fma2(w2r[k][1], qd1, s);
            s = fma2(w2r[k][2], qd2, s);
            s = fma2(w2r[k][3], qd3, s);
            float2 f = upk2(s);
            o[k] = f.x + f.y;
        }
        *((float4*)(out + (size_t)row * 1024 + e0)) =
            make_float4(o[0], o[1], o[2], o[3]);
    }
}

extern "C" void kernel_launch(void* const* d_in, const int* in_sizes, int n_in,
                              void* d_out, int out_size)
{
    const float* x  = (const float*)d_in[0];
    const float* W1 = (const float*)d_in[1];
    const float* b1 = (const float*)d_in[2];
    const float* qp = (const float*)d_in[3];
    const float* W2 = (const float*)d_in[4];
    const float* b2 = (const float*)d_in[5];
    float* out = (float*)d_out;

    const int nrows = in_sizes[0] / 1024;            // batch * seq_len
    const int nblocks = (nrows + 7) / 8;             // 8 rows per block

    ffq_kernel<<<nblocks, 256>>>(x, W1, b1, qp, W2, b2, out, nrows);
}

// round 12
// speedup vs baseline: 1.3464x; 1.3464x over previous
#include <cuda_runtime.h>
#include <cstdint>

#define FULL 0xffffffffu
typedef unsigned long long u64;

// ---- packed f32x2 helpers (Blackwell FFMA2 — only reachable via PTX) ----
__device__ __forceinline__ u64 pk2(float lo, float hi) {
    u64 r;
    asm("mov.b64 %0, {%1, %2};" : "=l"(r) : "f"(lo), "f"(hi));
    return r;
}
__device__ __forceinline__ float2 upk2(u64 p) {
    float2 v;
    asm("mov.b64 {%0, %1}, %2;" : "=f"(v.x), "=f"(v.y) : "l"(p));
    return v;
}
__device__ __forceinline__ u64 fma2(u64 a, u64 b, u64 c) {
    u64 d;
    asm("fma.rn.f32x2 %0, %1, %2, %3;" : "=l"(d) : "l"(a), "l"(b), "l"(c));
    return d;
}
__device__ __forceinline__ u64 mul2(u64 a, u64 b) {
    u64 d;
    asm("mul.rn.f32x2 %0, %1, %2;" : "=l"(d) : "l"(a), "l"(b));
    return d;
}

// Fused split-K kernel, 8 rows per 256-thread block, grid = nrows/8.
// Qubit octet lives in lane bits 2..4 (q = lane>>2) so that:
//  - W1 slot-k loads (row (lane>>2)^k, cols lane*4) come in 4-lane 64B chunks
//    (near-coalesced), unlike the R11 XOR layout on lane bits 0..2;
//  - the reduce-scatter is SEL-free with compile-time slot indices:
//      b=0: v[k]+=shfl_xor(v[k^1],4)   k in {0,2,4,6}
//      b=1: v[k]+=shfl_xor(v[k^2],8)   k in {0,4}
//      b=2: v[0]+=shfl_xor(v[4],16)
//      free: v[0]+=shfl_xor(v[0],1); v[0]+=shfl_xor(v[0],2)
//    After this every lane holds qubit (lane>>2)'s full warp sum in v[0].
// Quantum (threads 0..63): z = cos(th)cos(a) - sin(th)sin(phi)sin(a);
//   CNOT ring conjugated to Z-strings -> qout via octet prefix products.
// Phase 2 (R6 layout): e = wid*128 + c*32 + lane; W2 register-resident with
//   contiguous warp loads; bias folded; per row 2 LDS + 16 FFMA2 + 4 STG.32.
__global__ void __launch_bounds__(256, 3)
ffq_kernel(const float* __restrict__ x,  const float* __restrict__ W1,
           const float* __restrict__ b1, const float* __restrict__ qp,
           const float* __restrict__ W2, const float* __restrict__ b2,
           float* __restrict__ out, int nrows)
{
    __shared__ __align__(16) float part[8][8][8];   // [row][qubit][warp]
    __shared__ __align__(16) float sq[8][8];        // qout per row

    const int tid  = threadIdx.x;
    const int lane = tid & 31;
    const int wid  = tid >> 5;
    const int rowblk = blockIdx.x * 8;

    const int j0 = wid * 128 + lane * 4;   // this lane's 4 j's
    const int qoct = lane >> 2;            // qubit octet in lane bits 2..4

    // ---------------- Phase 1: split-K GEMM1, W1 reg-resident ----------------
    u64 wp0[8], wp1[8];
#pragma unroll
    for (int k = 0; k < 8; k++) {
        const int i = qoct ^ k;   // slot k of lane L <-> W1 row (L>>2)^k
        longlong2 w = __ldg((const longlong2*)(W1 + (size_t)i * 1024 + j0));
        wp0[k] = (u64)w.x;
        wp1[k] = (u64)w.y;
    }

#pragma unroll 4
    for (int rloc = 0; rloc < 8; rloc++) {
        const int row = min(rowblk + rloc, nrows - 1);
        longlong2 xv = __ldg((const longlong2*)(x + (size_t)row * 1024 + j0));
        const u64 x0 = (u64)xv.x, x1 = (u64)xv.y;

        float v[8];
#pragma unroll
        for (int k = 0; k < 8; k++) {
            u64 s = mul2(x0, wp0[k]);
            s = fma2(x1, wp1[k], s);
            float2 f = upk2(s);
            v[k] = f.x + f.y;
        }

        // SEL-free reduce-scatter (qubit bits = lane bits 2..4)
        v[0] += __shfl_xor_sync(FULL, v[1], 4, 32);
        v[2] += __shfl_xor_sync(FULL, v[3], 4, 32);
        v[4] += __shfl_xor_sync(FULL, v[5], 4, 32);
        v[6] += __shfl_xor_sync(FULL, v[7], 4, 32);
        v[0] += __shfl_xor_sync(FULL, v[2], 8, 32);
        v[4] += __shfl_xor_sync(FULL, v[6], 8, 32);
        v[0] += __shfl_xor_sync(FULL, v[4], 16, 32);
        v[0] += __shfl_xor_sync(FULL, v[0], 1, 32);
        v[0] += __shfl_xor_sync(FULL, v[0], 2, 32);

        if ((lane & 3) == 0) part[rloc][qoct][wid] = v[0];
    }
    __syncthreads();

    // ---------------- Quantum: one thread per (row, qubit) ----------------
    if (tid < 64) {
        const int r  = tid >> 3;
        const int qi = tid & 7;

        const float4 pa = *(const float4*)&part[r][qi][0];
        const float4 pb = *(const float4*)&part[r][qi][4];
        const float a = ((pa.x + pa.y) + (pa.z + pa.w))
                      + ((pb.x + pb.y) + (pb.z + pb.w)) + __ldg(b1 + qi);

        const float phi   = __ldg(qp + 3 * qi);
        const float theta = __ldg(qp + 3 * qi + 1);
        const float k1 = cosf(theta);
        const float k2 = sinf(theta) * sinf(phi);

        float sa, ca;
        __sincosf(a, &sa, &ca);
        const float z = k1 * ca - k2 * sa;

        // inclusive prefix product over each 8-lane octet
        float p = z;
#pragma unroll
        for (int d = 1; d < 8; d <<= 1) {
            float t = __shfl_up_sync(FULL, p, d, 8);
            if (qi >= d) p *= t;
        }
        // second scan with z0 -> 1 for qout[0] = z1..z7
        float wv = (qi == 0) ? 1.0f : z;
#pragma unroll
        for (int d = 1; d < 8; d <<= 1) {
            float t = __shfl_up_sync(FULL, wv, d, 8);
            if (qi >= d) wv *= t;
        }
        const float pb7 = __shfl_sync(FULL, wv, 7, 8);
        sq[r][qi] = (qi == 0) ? pb7 : p;
    }
    __syncthreads();

    // ---------------- Phase 2: GEMM2 (R6 layout), W2 reg-resident, bias folded ----------------
    u64 w2r[4][4];
    u64 bvp[4];
#pragma unroll
    for (int c = 0; c < 4; c++) {
        const int e = wid * 128 + c * 32 + lane;
        longlong2 a = __ldg((const longlong2*)(W2 + (size_t)e * 8));
        longlong2 b = __ldg((const longlong2*)(W2 + (size_t)e * 8 + 4));
        w2r[c][0] = (u64)a.x;
        w2r[c][1] = (u64)a.y;
        w2r[c][2] = (u64)b.x;
        w2r[c][3] = (u64)b.y;
        bvp[c] = pk2(__ldg(b2 + e), 0.0f);
    }

#pragma unroll 4
    for (int rloc = 0; rloc < 8; rloc++) {
        const int row = rowblk + rloc;
        if (row >= nrows) break;

        const longlong2* sp = (const longlong2*)sq[rloc];   // broadcast LDS x2
        longlong2 qa = sp[0], qb = sp[1];
        const u64 qd0 = (u64)qa.x, qd1 = (u64)qa.y;
        const u64 qd2 = (u64)qb.x, qd3 = (u64)qb.y;

        float* orow = out + (size_t)row * 1024 + wid * 128 + lane;
#pragma unroll
        for (int c = 0; c < 4; c++) {
            u64 s = fma2(w2r[c][0], qd0, bvp[c]);
            s = fma2(w2r[c][1], qd1, s);
            s = fma2(w2r[c][2], qd2, s);
            s = fma2(w2r[c][3], qd3, s);
            float2 f = upk2(s);
            orow[c * 32] = f.x + f.y;
        }
    }
}

extern "C" void kernel_launch(void* const* d_in, const int* in_sizes, int n_in,
                              void* d_out, int out_size)
{
    const float* x  = (const float*)d_in[0];
    const float* W1 = (const float*)d_in[1];
    const float* b1 = (const float*)d_in[2];
    const float* qp = (const float*)d_in[3];
    const float* W2 = (const float*)d_in[4];
    const float* b2 = (const float*)d_in[5];
    float* out = (float*)d_out;

    const int nrows = in_sizes[0] / 1024;            // batch * seq_len
    const int nblocks = (nrows + 7) / 8;             // 8 rows per block

    ffq_kernel<<<nblocks, 256>>>(x, W1, b1, qp, W2, b2, out, nrows);
}